// round 2
// baseline (speedup 1.0000x reference)
#include <cuda_runtime.h>

#define NNODES 50000
#define DIM 128
#define NEDGES 600000
#define NVROWS (NNODES*3)

#define GEMM_SMEM ((128*129 + 128*128)*4)

// ---- device scratch (static globals: allocation-free per harness rules) ----
__device__ float g_q [NNODES*DIM];
__device__ float g_k [NNODES*DIM];
__device__ float g_vs[NNODES*DIM];
__device__ float g_vv[NNODES*DIM];
__device__ float g_aggv[(size_t)NVROWS*DIM];
__device__ int   g_cnt[NNODES];
__device__ int   g_rowptr[NNODES+1];
__device__ int   g_colidx[NEDGES];

typedef unsigned long long u64;

// ---- packed fp32x2 helpers (Blackwell) ----
__device__ __forceinline__ u64 dup2(float x){
    u64 r; asm("mov.b64 %0, {%1, %1};" : "=l"(r) : "f"(x)); return r;
}
__device__ __forceinline__ u64 pair2(float x, float y){
    u64 r; asm("mov.b64 %0, {%1, %2};" : "=l"(r) : "f"(x), "f"(y)); return r;
}
__device__ __forceinline__ void fma2(u64 &d, u64 a, u64 b){
    asm("fma.rn.f32x2 %0, %1, %2, %0;" : "+l"(d) : "l"(a), "l"(b));
}
__device__ __forceinline__ void unpk(u64 v, float &lo, float &hi){
    asm("mov.b64 {%0, %1}, %2;" : "=f"(lo), "=f"(hi) : "l"(v));
}

// ============================================================================
// GEMM tile: C[128,128] = A[128,128] @ B[128,128] + bias (+ addend)
// 256 threads, per-thread 8 rows x 8 cols (cols c = tx + 16*j), f32x2 FMAs.
// K=128 fits entirely in smem -> single load phase, no mainloop barriers.
// ============================================================================
__device__ __forceinline__ void gemm_tile(
    const float* __restrict__ A,      // A + row0*DIM (row stride DIM)
    int vrows,                        // valid rows in this tile (<=128)
    const float* __restrict__ B,      // weight base at col-window, row stride bld
    int bld,
    const float* __restrict__ bias,   // at col-window base (128 entries)
    const float* __restrict__ addend, // nullable, addend + row0*DIM
    float* __restrict__ outp)         // outp + row0*DIM
{
    extern __shared__ float smem[];
    float* As = smem;                 // [128][129] (pad -> conflict-free a reads)
    float* Bs = smem + 128*129;       // [128][128]
    const int tid = threadIdx.x;

    // load A tile (coalesced float4 reads, scalar smem stores)
    #pragma unroll
    for (int i = 0; i < 16; i++){
        int fidx = i*256 + tid;
        int r  = fidx >> 5;
        int kq = fidx & 31;
        float4 av = make_float4(0.f, 0.f, 0.f, 0.f);
        if (r < vrows) av = *(const float4*)(A + (size_t)r*DIM + kq*4);
        float* dst = As + r*129 + kq*4;
        dst[0]=av.x; dst[1]=av.y; dst[2]=av.z; dst[3]=av.w;
    }
    // load B tile (coalesced float4 both sides)
    #pragma unroll
    for (int i = 0; i < 16; i++){
        int fidx = i*256 + tid;
        int kk = fidx >> 5;
        int cq = fidx & 31;
        float4 bv = *(const float4*)(B + (size_t)kk*bld + cq*4);
        *(float4*)(Bs + kk*128 + cq*4) = bv;
    }
    __syncthreads();

    const int tx = tid & 15;   // col group: cols tx + 16*j, j=0..7
    const int ty = tid >> 4;   // row group: rows ty*8 .. ty*8+7

    u64 acc[8][4];
    #pragma unroll
    for (int r = 0; r < 8; r++)
        #pragma unroll
        for (int p = 0; p < 4; p++) acc[r][p] = 0ull;

    const float* arow = As + (ty*8)*129;
    const float* bcol = Bs + tx;

    #pragma unroll 4
    for (int k = 0; k < 128; k++){
        u64 ap[8];
        #pragma unroll
        for (int j = 0; j < 8; j++) ap[j] = dup2(arow[j*129 + k]);
        u64 bp[4];
        #pragma unroll
        for (int p = 0; p < 4; p++)
            bp[p] = pair2(bcol[k*128 + 32*p], bcol[k*128 + 32*p + 16]);
        #pragma unroll
        for (int r = 0; r < 8; r++)
            #pragma unroll
            for (int p = 0; p < 4; p++)
                fma2(acc[r][p], ap[r], bp[p]);
    }

    // epilogue
    float blo[4], bhi[4];
    #pragma unroll
    for (int p = 0; p < 4; p++){
        blo[p] = bias[tx + 32*p];
        bhi[p] = bias[tx + 32*p + 16];
    }
    #pragma unroll
    for (int r = 0; r < 8; r++){
        int row = ty*8 + r;
        if (row < vrows){
            size_t base = (size_t)row*DIM;
            #pragma unroll
            for (int p = 0; p < 4; p++){
                float lo, hi; unpk(acc[r][p], lo, hi);
                int c0 = tx + 32*p;
                lo += blo[p]; hi += bhi[p];
                if (addend){
                    lo += addend[base + c0];
                    hi += addend[base + c0 + 16];
                }
                outp[base + c0]      = lo;
                outp[base + c0 + 16] = hi;
            }
        }
    }
}

// QKV: fused [N,128] @ [128,512]; blockIdx.y selects q / k / v_s / v_v column block
__global__ void __launch_bounds__(256, 1) gemm_qkv_kernel(
    const float* __restrict__ s,
    const float* __restrict__ Wq,  const float* __restrict__ bq,
    const float* __restrict__ Wkv, const float* __restrict__ bkv)
{
    int row0 = blockIdx.x * 128;
    int vrows = NNODES - row0; if (vrows > 128) vrows = 128;
    int cb = blockIdx.y;
    const float* B; int bld; const float* bias; float* outp;
    if (cb == 0){ B = Wq; bld = DIM; bias = bq; outp = g_q; }
    else {
        B   = Wkv + (cb-1)*DIM;
        bld = 3*DIM;
        bias = bkv + (cb-1)*DIM;
        outp = (cb == 1) ? g_k : ((cb == 2) ? g_vs : g_vv);
    }
    gemm_tile(s + (size_t)row0*DIM, vrows, B, bld, bias, nullptr,
              outp + (size_t)row0*DIM);
}

// v_out = v + agg_v @ Wvec + bvec   ([150000,128] @ [128,128])
__global__ void __launch_bounds__(256, 1) gemm_vout_kernel(
    const float* __restrict__ v,
    const float* __restrict__ Wvec, const float* __restrict__ bvec,
    float* __restrict__ outv)
{
    int row0 = blockIdx.x * 128;
    int vrows = NVROWS - row0; if (vrows > 128) vrows = 128;
    gemm_tile(g_aggv + (size_t)row0*DIM, vrows, Wvec, DIM, bvec,
              v + (size_t)row0*DIM, outv + (size_t)row0*DIM);
}

// ============================================================================
// CSR build: zero -> histogram -> single-block scan -> scatter
// ============================================================================
__global__ void zero_cnt_kernel(){
    int i = blockIdx.x*blockDim.x + threadIdx.x;
    if (i < NNODES) g_cnt[i] = 0;
}

__global__ void hist_kernel(const int* __restrict__ ei){
    int e = blockIdx.x*blockDim.x + threadIdx.x;
    if (e < NEDGES) atomicAdd(&g_cnt[ei[e]], 1);
}

__global__ void scan_kernel(){
    __shared__ int sh[1024];
    int tid = threadIdx.x;
    int carry = 0;
    for (int base = 0; base < NNODES; base += 1024){
        int i = base + tid;
        int x = (i < NNODES) ? g_cnt[i] : 0;
        sh[tid] = x;
        __syncthreads();
        #pragma unroll
        for (int off = 1; off < 1024; off <<= 1){
            int val = (tid >= off) ? sh[tid - off] : 0;
            __syncthreads();
            sh[tid] += val;
            __syncthreads();
        }
        int incl = sh[tid];
        if (i < NNODES){
            g_rowptr[i] = carry + incl - x;  // exclusive
            g_cnt[i] = 0;                    // reuse as scatter cursor
        }
        int tot = sh[1023];
        __syncthreads();
        carry += tot;
    }
    if (tid == 0) g_rowptr[NNODES] = carry;
}

__global__ void scatter_kernel(const int* __restrict__ ei){
    int e = blockIdx.x*blockDim.x + threadIdx.x;
    if (e < NEDGES){
        int r = ei[e];
        int c = ei[NEDGES + e];
        int pos = g_rowptr[r] + atomicAdd(&g_cnt[r], 1);
        g_colidx[pos] = c;
    }
}

// ============================================================================
// Edge aggregation: one warp per destination node (CSR row). No atomics.
// lane owns dims [lane*4, lane*4+4). Edge loop unrolled x2: the two edges'
// gathers and shfl butterflies are independent -> 12 outstanding float4
// gathers + overlapped reduce trees per warp.
// ============================================================================
struct EdgeAcc {
    float4 sa, va0, va1, va2;
};

__device__ __forceinline__ float edge_dot(const float4& q4, const float4& k4){
    float p = q4.x*k4.x + q4.y*k4.y + q4.z*k4.z + q4.w*k4.w;
    #pragma unroll
    for (int off = 16; off; off >>= 1)
        p += __shfl_xor_sync(0xffffffffu, p, off);
    return p;
}

__device__ __forceinline__ void edge_accum(
    EdgeAcc& A, float p, const float4& vs4, const float4& vv4,
    const float4& v0, const float4& v1, const float4& v2)
{
    A.sa.x += p*vs4.x; A.sa.y += p*vs4.y; A.sa.z += p*vs4.z; A.sa.w += p*vs4.w;
    float tx_ = p*vv4.x, ty_ = p*vv4.y, tz_ = p*vv4.z, tw_ = p*vv4.w;
    A.va0.x += tx_*v0.x; A.va0.y += ty_*v0.y; A.va0.z += tz_*v0.z; A.va0.w += tw_*v0.w;
    A.va1.x += tx_*v1.x; A.va1.y += ty_*v1.y; A.va1.z += tz_*v1.z; A.va1.w += tw_*v1.w;
    A.va2.x += tx_*v2.x; A.va2.y += ty_*v2.y; A.va2.z += tz_*v2.z; A.va2.w += tw_*v2.w;
}

__global__ void __launch_bounds__(256) agg_kernel(
    const float* __restrict__ s,
    const float* __restrict__ v,
    float* __restrict__ out_s)
{
    int warp = (blockIdx.x * blockDim.x + threadIdx.x) >> 5;
    int lane = threadIdx.x & 31;
    if (warp >= NNODES) return;
    const int n = warp;
    const int d = lane * 4;

    float4 q4 = *(const float4*)(g_q + (size_t)n*DIM + d);
    EdgeAcc A;
    A.sa = make_float4(0.f, 0.f, 0.f, 0.f);
    A.va0 = A.sa; A.va1 = A.sa; A.va2 = A.sa;

    const int e0 = g_rowptr[n], e1 = g_rowptr[n+1];
    int e = e0;
    for (; e + 2 <= e1; e += 2){
        int ca = g_colidx[e];
        int cb = g_colidx[e+1];
        // issue all 12 gathers before any reduce
        float4 ka  = *(const float4*)(g_k  + (size_t)ca*DIM + d);
        float4 kb  = *(const float4*)(g_k  + (size_t)cb*DIM + d);
        float4 vsa = *(const float4*)(g_vs + (size_t)ca*DIM + d);
        float4 vsb = *(const float4*)(g_vs + (size_t)cb*DIM + d);
        float4 vva = *(const float4*)(g_vv + (size_t)ca*DIM + d);
        float4 vvb = *(const float4*)(g_vv + (size_t)cb*DIM + d);
        const float* vba = v + (size_t)ca*3*DIM + d;
        const float* vbb = v + (size_t)cb*3*DIM + d;
        float4 a0 = *(const float4*)(vba);
        float4 a1 = *(const float4*)(vba + DIM);
        float4 a2 = *(const float4*)(vba + 2*DIM);
        float4 b0 = *(const float4*)(vbb);
        float4 b1 = *(const float4*)(vbb + DIM);
        float4 b2 = *(const float4*)(vbb + 2*DIM);

        // two independent shfl trees (compiler interleaves them)
        float pa_part = q4.x*ka.x + q4.y*ka.y + q4.z*ka.z + q4.w*ka.w;
        float pb_part = q4.x*kb.x + q4.y*kb.y + q4.z*kb.z + q4.w*kb.w;
        #pragma unroll
        for (int off = 16; off; off >>= 1){
            pa_part += __shfl_xor_sync(0xffffffffu, pa_part, off);
            pb_part += __shfl_xor_sync(0xffffffffu, pb_part, off);
        }
        edge_accum(A, pa_part, vsa, vva, a0, a1, a2);
        edge_accum(A, pb_part, vsb, vvb, b0, b1, b2);
    }
    if (e < e1){
        int c = g_colidx[e];
        float4 k4  = *(const float4*)(g_k  + (size_t)c*DIM + d);
        float4 vs4 = *(const float4*)(g_vs + (size_t)c*DIM + d);
        float4 vv4 = *(const float4*)(g_vv + (size_t)c*DIM + d);
        const float* vb = v + (size_t)c*3*DIM + d;
        float4 v0 = *(const float4*)(vb);
        float4 v1 = *(const float4*)(vb + DIM);
        float4 v2 = *(const float4*)(vb + 2*DIM);
        float p = edge_dot(q4, k4);
        edge_accum(A, p, vs4, vv4, v0, v1, v2);
    }

    float4 sv = *(const float4*)(s + (size_t)n*DIM + d);
    float4 so = make_float4(sv.x + A.sa.x, sv.y + A.sa.y,
                            sv.z + A.sa.z, sv.w + A.sa.w);
    *(float4*)(out_s + (size_t)n*DIM + d) = so;

    float* ab = g_aggv + (size_t)n*3*DIM + d;
    *(float4*)(ab)         = A.va0;
    *(float4*)(ab + DIM)   = A.va1;
    *(float4*)(ab + 2*DIM) = A.va2;
}

// ============================================================================
extern "C" void kernel_launch(void* const* d_in, const int* in_sizes, int n_in,
                              void* d_out, int out_size)
{
    (void)in_sizes; (void)n_in; (void)out_size;
    const float* s    = (const float*)d_in[0];
    const float* v    = (const float*)d_in[1];
    const int*   ei   = (const int*)  d_in[2];
    const float* Wq   = (const float*)d_in[3];
    const float* bq   = (const float*)d_in[4];
    const float* Wkv  = (const float*)d_in[5];
    const float* bkv  = (const float*)d_in[6];
    const float* Wvec = (const float*)d_in[7];
    const float* bvec = (const float*)d_in[8];
    float* out_s = (float*)d_out;
    float* out_v = out_s + (size_t)NNODES*DIM;

    cudaFuncSetAttribute((const void*)gemm_qkv_kernel,
                         cudaFuncAttributeMaxDynamicSharedMemorySize, GEMM_SMEM);
    cudaFuncSetAttribute((const void*)gemm_vout_kernel,
                         cudaFuncAttributeMaxDynamicSharedMemorySize, GEMM_SMEM);

    // CSR build
    zero_cnt_kernel<<<(NNODES + 255)/256, 256>>>();
    hist_kernel   <<<(NEDGES + 255)/256, 256>>>(ei);
    scan_kernel   <<<1, 1024>>>();
    scatter_kernel<<<(NEDGES + 255)/256, 256>>>(ei);

    // projections
    gemm_qkv_kernel<<<dim3((NNODES + 127)/128, 4), 256, GEMM_SMEM>>>(s, Wq, bq, Wkv, bkv);

    // edge aggregation (warp per node): writes s_out + agg_v
    agg_kernel<<<(NNODES*32 + 255)/256, 256>>>(s, v, out_s);

    // v_out = v + agg_v @ Wvec + bvec
    gemm_vout_kernel<<<(NVROWS + 127)/128, 256, GEMM_SMEM>>>(v, Wvec, bvec, out_v);
}

// round 3
// speedup vs baseline: 1.0650x; 1.0650x over previous
#include <cuda_runtime.h>

#define NNODES 50000
#define DIM 128
#define NEDGES 600000
#define NVROWS (NNODES*3)

// As padded to 132 floats/row (16B-aligned float4 stores, even offset for LDS.64)
#define AS_LD 132
#define GEMM_SMEM ((128*AS_LD + 128*128)*4)

// ---- device scratch ----
__device__ float g_q  [(size_t)NNODES*128];
__device__ float g_kvs[(size_t)NNODES*256];   // [n][0:128)=k, [128:256)=v_s
__device__ float g_u  [(size_t)NNODES*384];   // [n][j][c] = v_v[n][c]*v[n][j][c]
__device__ float g_aggv[(size_t)NVROWS*128];
__device__ int   g_cnt[NNODES];
__device__ int   g_rowptr[NNODES+1];
__device__ int   g_colidx[NEDGES];

typedef unsigned long long u64;

// ---- packed fp32x2 helpers (Blackwell) ----
__device__ __forceinline__ u64 dup2(float x){
    u64 r; asm("mov.b64 %0, {%1, %1};" : "=l"(r) : "f"(x)); return r;
}
__device__ __forceinline__ void fma2(u64 &d, u64 a, u64 b){
    asm("fma.rn.f32x2 %0, %1, %2, %0;" : "+l"(d) : "l"(a), "l"(b));
}
__device__ __forceinline__ void unpk(u64 v, float &lo, float &hi){
    asm("mov.b64 {%0, %1}, %2;" : "=f"(lo), "=f"(hi) : "l"(v));
}

// ============================================================================
// GEMM tile: C[128,128] = A[vrows,128] @ B[128,128] (+bias, +addend or u-mode)
// 256 threads; thread (tx,ty) owns rows ty*8..+7, col pairs (2tx+32p, +1).
// b-operand is a packed f32x2 loaded with one LDS.64 (adjacent columns).
// K=128 resident in smem -> single load phase, no mainloop barriers.
// UMODE: C is v_v tile; write u[j] = C * v[row][j][:] for j=0..2 (ld 384).
// ============================================================================
template<int UMODE>
__device__ __forceinline__ void gemm_tile(
    const float* __restrict__ A, int vrows,
    const float* __restrict__ B, int bld,
    const float* __restrict__ bias,
    const float* __restrict__ addend,   // nullable, ld = old_
    float* __restrict__ outp, int old_,
    const float* __restrict__ vsrc)     // UMODE only, ld 384
{
    extern __shared__ float smem[];
    float* As = smem;                   // [128][AS_LD]
    float* Bs = smem + 128*AS_LD;       // [128][128]
    const int tid = threadIdx.x;

    #pragma unroll
    for (int i = 0; i < 16; i++){
        int fidx = i*256 + tid;
        int r  = fidx >> 5;
        int kq = fidx & 31;
        float4 av = make_float4(0.f, 0.f, 0.f, 0.f);
        if (r < vrows) av = *(const float4*)(A + (size_t)r*128 + kq*4);
        *(float4*)(As + r*AS_LD + kq*4) = av;
    }
    #pragma unroll
    for (int i = 0; i < 16; i++){
        int fidx = i*256 + tid;
        int kk = fidx >> 5;
        int cq = fidx & 31;
        float4 bv = *(const float4*)(B + (size_t)kk*bld + cq*4);
        *(float4*)(Bs + kk*128 + cq*4) = bv;
    }
    __syncthreads();

    const int tx = tid & 15;
    const int ty = tid >> 4;

    u64 acc[8][4];
    #pragma unroll
    for (int r = 0; r < 8; r++)
        #pragma unroll
        for (int p = 0; p < 4; p++) acc[r][p] = 0ull;

    const float* arow  = As + (ty*8)*AS_LD;
    const float* bbase = Bs + 2*tx;

    #pragma unroll 2
    for (int kk = 0; kk < 64; kk++){
        const int k0 = 2*kk;
        float2 av[8];
        #pragma unroll
        for (int j = 0; j < 8; j++)
            av[j] = *(const float2*)(arow + j*AS_LD + k0);
        u64 b0[4], b1[4];
        #pragma unroll
        for (int p = 0; p < 4; p++){
            b0[p] = *(const u64*)(bbase + (size_t)(k0  )*128 + 32*p);
            b1[p] = *(const u64*)(bbase + (size_t)(k0+1)*128 + 32*p);
        }
        #pragma unroll
        for (int j = 0; j < 8; j++){
            u64 a0 = dup2(av[j].x);
            u64 a1 = dup2(av[j].y);
            #pragma unroll
            for (int p = 0; p < 4; p++){
                fma2(acc[j][p], a0, b0[p]);
                fma2(acc[j][p], a1, b1[p]);
            }
        }
    }

    float2 bi[4];
    #pragma unroll
    for (int p = 0; p < 4; p++)
        bi[p] = *(const float2*)(bias + 2*tx + 32*p);

    #pragma unroll
    for (int r = 0; r < 8; r++){
        int row = ty*8 + r;
        if (row >= vrows) continue;
        if (UMODE){
            const float* vr = vsrc + (size_t)row*384;
            float*       ur = outp + (size_t)row*384;
            #pragma unroll
            for (int p = 0; p < 4; p++){
                float g0, g1; unpk(acc[r][p], g0, g1);
                g0 += bi[p].x; g1 += bi[p].y;
                int c0 = 2*tx + 32*p;
                #pragma unroll
                for (int j = 0; j < 3; j++){
                    float2 vv2 = *(const float2*)(vr + j*128 + c0);
                    float2 o; o.x = g0*vv2.x; o.y = g1*vv2.y;
                    *(float2*)(ur + j*128 + c0) = o;
                }
            }
        } else {
            float* orow = outp + (size_t)row*old_;
            const float* ar = addend ? (addend + (size_t)row*old_) : nullptr;
            #pragma unroll
            for (int p = 0; p < 4; p++){
                float lo, hi; unpk(acc[r][p], lo, hi);
                int c0 = 2*tx + 32*p;
                lo += bi[p].x; hi += bi[p].y;
                if (ar){
                    float2 a2 = *(const float2*)(ar + c0);
                    lo += a2.x; hi += a2.y;
                }
                float2 o; o.x = lo; o.y = hi;
                *(float2*)(orow + c0) = o;
            }
        }
    }
}

// QKV: [N,128] @ [128,512]; blockIdx.y: 0=q, 1=k, 2=v_s, 3=v_v(->u)
__global__ void __launch_bounds__(256, 1) gemm_qkv_kernel(
    const float* __restrict__ s, const float* __restrict__ v,
    const float* __restrict__ Wq,  const float* __restrict__ bq,
    const float* __restrict__ Wkv, const float* __restrict__ bkv)
{
    int row0 = blockIdx.x * 128;
    int vrows = NNODES - row0; if (vrows > 128) vrows = 128;
    const float* Atile = s + (size_t)row0*128;
    int cb = blockIdx.y;
    if (cb == 0){
        gemm_tile<0>(Atile, vrows, Wq, 128, bq, nullptr,
                     g_q + (size_t)row0*128, 128, nullptr);
    } else if (cb == 1){
        gemm_tile<0>(Atile, vrows, Wkv, 384, bkv, nullptr,
                     g_kvs + (size_t)row0*256, 256, nullptr);
    } else if (cb == 2){
        gemm_tile<0>(Atile, vrows, Wkv + 128, 384, bkv + 128, nullptr,
                     g_kvs + (size_t)row0*256 + 128, 256, nullptr);
    } else {
        gemm_tile<1>(Atile, vrows, Wkv + 256, 384, bkv + 256, nullptr,
                     g_u + (size_t)row0*384, 384, v + (size_t)row0*384);
    }
}

// v_out = v + agg_v @ Wvec + bvec   ([150000,128] @ [128,128])
__global__ void __launch_bounds__(256, 1) gemm_vout_kernel(
    const float* __restrict__ v,
    const float* __restrict__ Wvec, const float* __restrict__ bvec,
    float* __restrict__ outv)
{
    int row0 = blockIdx.x * 128;
    int vrows = NVROWS - row0; if (vrows > 128) vrows = 128;
    gemm_tile<0>(g_aggv + (size_t)row0*128, vrows, Wvec, 128, bvec,
                 v + (size_t)row0*128, outv + (size_t)row0*128, 128, nullptr);
}

// ============================================================================
// CSR build
// ============================================================================
__global__ void zero_cnt_kernel(){
    int i = blockIdx.x*blockDim.x + threadIdx.x;
    if (i < NNODES) g_cnt[i] = 0;
}

__global__ void hist_kernel(const int* __restrict__ ei){
    int e = blockIdx.x*blockDim.x + threadIdx.x;
    if (e < NEDGES) atomicAdd(&g_cnt[ei[e]], 1);
}

// 1024-thread warp-shuffle scan over 50000 counts (49 tiles, 3 barriers each)
__global__ void scan_kernel(){
    __shared__ int wsum[32];
    __shared__ int tot_s;
    int tid = threadIdx.x, lane = tid & 31, wid = tid >> 5;
    int carry = 0;
    for (int base = 0; base < NNODES; base += 1024){
        int i = base + tid;
        int x = (i < NNODES) ? g_cnt[i] : 0;
        int incl = x;
        #pragma unroll
        for (int off = 1; off < 32; off <<= 1){
            int y = __shfl_up_sync(0xffffffffu, incl, off);
            if (lane >= off) incl += y;
        }
        if (lane == 31) wsum[wid] = incl;
        __syncthreads();
        if (wid == 0){
            int wv = wsum[lane];
            int winc = wv;
            #pragma unroll
            for (int off = 1; off < 32; off <<= 1){
                int y = __shfl_up_sync(0xffffffffu, winc, off);
                if (lane >= off) winc += y;
            }
            wsum[lane] = winc - wv;      // exclusive warp prefix
            if (lane == 31) tot_s = winc;
        }
        __syncthreads();
        if (i < NNODES){
            g_rowptr[i] = carry + wsum[wid] + (incl - x);
            g_cnt[i] = 0;                // reuse as scatter cursor
        }
        carry += tot_s;
        __syncthreads();
    }
    if (tid == 0) g_rowptr[NNODES] = carry;
}

__global__ void scatter_kernel(const int* __restrict__ ei){
    int e = blockIdx.x*blockDim.x + threadIdx.x;
    if (e < NEDGES){
        int r = ei[e];
        int c = ei[NEDGES + e];
        int pos = g_rowptr[r] + atomicAdd(&g_cnt[r], 1);
        g_colidx[pos] = c;
    }
}

// ============================================================================
// Edge aggregation: warp per node, no atomics. Per edge: 5 float4 gathers
// (k, v_s from g_kvs; u0..u2 from g_u) = 2560 B/edge. Edge loop unrolled x2.
// ============================================================================
struct EdgeAcc { float4 sa, va0, va1, va2; };

__device__ __forceinline__ void edge_accum(
    EdgeAcc& A, float p, const float4& vs4,
    const float4& u0, const float4& u1, const float4& u2)
{
    A.sa.x  += p*vs4.x; A.sa.y  += p*vs4.y; A.sa.z  += p*vs4.z; A.sa.w  += p*vs4.w;
    A.va0.x += p*u0.x;  A.va0.y += p*u0.y;  A.va0.z += p*u0.z;  A.va0.w += p*u0.w;
    A.va1.x += p*u1.x;  A.va1.y += p*u1.y;  A.va1.z += p*u1.z;  A.va1.w += p*u1.w;
    A.va2.x += p*u2.x;  A.va2.y += p*u2.y;  A.va2.z += p*u2.z;  A.va2.w += p*u2.w;
}

__global__ void __launch_bounds__(256) agg_kernel(
    const float* __restrict__ s,
    float* __restrict__ out_s)
{
    int warp = (blockIdx.x * blockDim.x + threadIdx.x) >> 5;
    int lane = threadIdx.x & 31;
    if (warp >= NNODES) return;
    const int n = warp;
    const int d = lane * 4;

    float4 q4 = *(const float4*)(g_q + (size_t)n*128 + d);
    EdgeAcc A;
    A.sa = make_float4(0.f, 0.f, 0.f, 0.f);
    A.va0 = A.sa; A.va1 = A.sa; A.va2 = A.sa;

    const int e0 = g_rowptr[n], e1 = g_rowptr[n+1];
    int e = e0;
    for (; e + 2 <= e1; e += 2){
        int ca = g_colidx[e];
        int cb = g_colidx[e+1];
        const float* pka = g_kvs + (size_t)ca*256 + d;
        const float* pkb = g_kvs + (size_t)cb*256 + d;
        const float* pua = g_u   + (size_t)ca*384 + d;
        const float* pub = g_u   + (size_t)cb*384 + d;
        float4 ka  = *(const float4*)(pka);
        float4 kb  = *(const float4*)(pkb);
        float4 vsa = *(const float4*)(pka + 128);
        float4 vsb = *(const float4*)(pkb + 128);
        float4 a0 = *(const float4*)(pua);
        float4 a1 = *(const float4*)(pua + 128);
        float4 a2 = *(const float4*)(pua + 256);
        float4 b0 = *(const float4*)(pub);
        float4 b1 = *(const float4*)(pub + 128);
        float4 b2 = *(const float4*)(pub + 256);

        float pa = q4.x*ka.x + q4.y*ka.y + q4.z*ka.z + q4.w*ka.w;
        float pb = q4.x*kb.x + q4.y*kb.y + q4.z*kb.z + q4.w*kb.w;
        #pragma unroll
        for (int off = 16; off; off >>= 1){
            pa += __shfl_xor_sync(0xffffffffu, pa, off);
            pb += __shfl_xor_sync(0xffffffffu, pb, off);
        }
        edge_accum(A, pa, vsa, a0, a1, a2);
        edge_accum(A, pb, vsb, b0, b1, b2);
    }
    if (e < e1){
        int c = g_colidx[e];
        const float* pk = g_kvs + (size_t)c*256 + d;
        const float* pu = g_u   + (size_t)c*384 + d;
        float4 k4  = *(const float4*)(pk);
        float4 vs4 = *(const float4*)(pk + 128);
        float4 u0 = *(const float4*)(pu);
        float4 u1 = *(const float4*)(pu + 128);
        float4 u2 = *(const float4*)(pu + 256);
        float p = q4.x*k4.x + q4.y*k4.y + q4.z*k4.z + q4.w*k4.w;
        #pragma unroll
        for (int off = 16; off; off >>= 1)
            p += __shfl_xor_sync(0xffffffffu, p, off);
        edge_accum(A, p, vs4, u0, u1, u2);
    }

    float4 sv = *(const float4*)(s + (size_t)n*128 + d);
    float4 so = make_float4(sv.x + A.sa.x, sv.y + A.sa.y,
                            sv.z + A.sa.z, sv.w + A.sa.w);
    *(float4*)(out_s + (size_t)n*128 + d) = so;

    float* ab = g_aggv + (size_t)n*384 + d;
    *(float4*)(ab)       = A.va0;
    *(float4*)(ab + 128) = A.va1;
    *(float4*)(ab + 256) = A.va2;
}

// ============================================================================
extern "C" void kernel_launch(void* const* d_in, const int* in_sizes, int n_in,
                              void* d_out, int out_size)
{
    (void)in_sizes; (void)n_in; (void)out_size;
    const float* s    = (const float*)d_in[0];
    const float* v    = (const float*)d_in[1];
    const int*   ei   = (const int*)  d_in[2];
    const float* Wq   = (const float*)d_in[3];
    const float* bq   = (const float*)d_in[4];
    const float* Wkv  = (const float*)d_in[5];
    const float* bkv  = (const float*)d_in[6];
    const float* Wvec = (const float*)d_in[7];
    const float* bvec = (const float*)d_in[8];
    float* out_s = (float*)d_out;
    float* out_v = out_s + (size_t)NNODES*128;

    cudaFuncSetAttribute((const void*)gemm_qkv_kernel,
                         cudaFuncAttributeMaxDynamicSharedMemorySize, GEMM_SMEM);
    cudaFuncSetAttribute((const void*)gemm_vout_kernel,
                         cudaFuncAttributeMaxDynamicSharedMemorySize, GEMM_SMEM);

    // CSR build
    zero_cnt_kernel<<<(NNODES + 255)/256, 256>>>();
    hist_kernel   <<<(NEDGES + 255)/256, 256>>>(ei);
    scan_kernel   <<<1, 1024>>>();
    scatter_kernel<<<(NEDGES + 255)/256, 256>>>(ei);

    // projections (q, k, v_s, and u = v_v ⊙ v fused in epilogue)
    gemm_qkv_kernel<<<dim3((NNODES + 127)/128, 4), 256, GEMM_SMEM>>>(
        s, v, Wq, bq, Wkv, bkv);

    // edge aggregation (warp per node): writes s_out + g_aggv
    agg_kernel<<<(NNODES*32 + 255)/256, 256>>>(s, out_s);

    // v_out = v + agg_v @ Wvec + bvec
    gemm_vout_kernel<<<(NVROWS + 127)/128, 256, GEMM_SMEM>>>(v, Wvec, bvec, out_v);
}